// round 3
// baseline (speedup 1.0000x reference)
#include <cuda_runtime.h>
#include <cuda_bf16.h>

#define BOX 256
#define KS 9
#define PNT 20000
#define NB 16
#define NN 32
#define NL 3
#define LAT 8

// Shared-memory layout offsets (floats)
#define S_W1   0        // linamp1_W   [32*4]   = 128
#define S_AW   128      // ampblock_W  [3*1024] = 3072
#define S_AB   3200     // ampblock_b  [96]
#define S_W2   3296     // linamp2_W   [32]
#define S_L0   3328     // lin0_W      [320]
#define S_DW   3648     // deform_W    [3072]
#define S_DB   6720     // deform_b    [96]
#define S_A1   6816     // lin1a_W     [96]
#define S_B1   6912     // lin1b_W     [9]
#define S_K2   6921     // k2          [81]
#define S_TOT  7008

__global__ __launch_bounds__(256) void decoder_kernel(
    const float* __restrict__ z,          // [16,8]
    const float* __restrict__ r,          // [16,3,3]
    const float* __restrict__ pos,        // [20000,3]
    const float* __restrict__ amp,        // [1]
    const float* __restrict__ linamp1_W,  // [32,4]
    const float* __restrict__ ampblock_W, // [3,32,32]
    const float* __restrict__ ampblock_b, // [3,32]
    const float* __restrict__ linamp2_W,  // [1,32]
    const float* __restrict__ linamp2_b,  // [1]
    const float* __restrict__ lin0_W,     // [32,10]
    const float* __restrict__ deform_W,   // [3,32,32]
    const float* __restrict__ deform_b,   // [3,32]
    const float* __restrict__ lin1a_W,    // [3,32]
    const float* __restrict__ lin1b_W,    // [3,3]
    const float* __restrict__ k2,         // [9,9]
    float* __restrict__ out_img,          // [16,256,256]
    float* __restrict__ out_posdef,       // [16,20000,3]
    float* __restrict__ out_res,          // [16,20000,3]
    float* __restrict__ out_ampc,         // [16,20000]
    int write_extras)
{
    __shared__ float s[S_TOT];
    const int t = threadIdx.x;

    // Cooperative weight staging
    for (int i = t; i < 128;  i += 256) s[S_W1 + i] = linamp1_W[i];
    for (int i = t; i < 3072; i += 256) s[S_AW + i] = ampblock_W[i];
    for (int i = t; i < 96;   i += 256) s[S_AB + i] = ampblock_b[i];
    for (int i = t; i < 32;   i += 256) s[S_W2 + i] = linamp2_W[i];
    for (int i = t; i < 320;  i += 256) s[S_L0 + i] = lin0_W[i];
    for (int i = t; i < 3072; i += 256) s[S_DW + i] = deform_W[i];
    for (int i = t; i < 96;   i += 256) s[S_DB + i] = deform_b[i];
    for (int i = t; i < 96;   i += 256) s[S_A1 + i] = lin1a_W[i];
    for (int i = t; i < 9;    i += 256) s[S_B1 + i] = lin1b_W[i];
    for (int i = t; i < 81;   i += 256) s[S_K2 + i] = k2[i];
    __syncthreads();

    const int idx = blockIdx.x * 256 + t;
    if (idx >= NB * PNT) return;
    const int b = idx / PNT;
    const int p = idx - b * PNT;

    const float px = pos[p * 3 + 0];
    const float py = pos[p * 3 + 1];
    const float pz = pos[p * 3 + 2];

    float x[NN];
    float y[NN];

    // ---------------- amplitude head ----------------
    {
        const float cz = z[b * LAT + (LAT - 1)];
        #pragma unroll
        for (int j = 0; j < NN; j++) {
            const float4 w = *reinterpret_cast<const float4*>(&s[S_W1 + j * 4]);
            x[j] = fmaf(w.x, px, fmaf(w.y, py, fmaf(w.z, pz, w.w * cz)));
        }
        #pragma unroll
        for (int l = 0; l < NL; l++) {
            #pragma unroll
            for (int j = 0; j < NN; j++) {
                const float4* wr = reinterpret_cast<const float4*>(&s[S_AW + l * 1024 + j * 32]);
                float a = s[S_AB + l * 32 + j];
                #pragma unroll
                for (int i = 0; i < 8; i++) {
                    const float4 w = wr[i];
                    a = fmaf(w.x, x[4 * i + 0], a);
                    a = fmaf(w.y, x[4 * i + 1], a);
                    a = fmaf(w.z, x[4 * i + 2], a);
                    a = fmaf(w.w, x[4 * i + 3], a);
                }
                y[j] = fmaxf(a, 0.0f) + x[j];
            }
            #pragma unroll
            for (int j = 0; j < NN; j++) x[j] = y[j];
        }
    }
    float sacc = linamp2_b[0];
    #pragma unroll
    for (int j = 0; j < NN; j++) sacc = fmaf(s[S_W2 + j], x[j], sacc);
    const float amp_corr = 1.0f / (1.0f + expf(-sacc));

    // ---------------- deformation head ----------------
    float in10[10];
    in10[0] = px; in10[1] = py; in10[2] = pz;
    #pragma unroll
    for (int i = 0; i < LAT - 1; i++) in10[3 + i] = z[b * LAT + i];

    #pragma unroll
    for (int j = 0; j < NN; j++) {
        const float* wr = &s[S_L0 + j * 10];
        float a = 0.0f;
        #pragma unroll
        for (int i = 0; i < 10; i++) a = fmaf(wr[i], in10[i], a);
        x[j] = a;
    }
    #pragma unroll
    for (int l = 0; l < NL; l++) {
        #pragma unroll
        for (int j = 0; j < NN; j++) {
            const float4* wr = reinterpret_cast<const float4*>(&s[S_DW + l * 1024 + j * 32]);
            float a = s[S_DB + l * 32 + j];
            #pragma unroll
            for (int i = 0; i < 8; i++) {
                const float4 w = wr[i];
                a = fmaf(w.x, x[4 * i + 0], a);
                a = fmaf(w.y, x[4 * i + 1], a);
                a = fmaf(w.z, x[4 * i + 2], a);
                a = fmaf(w.w, x[4 * i + 3], a);
            }
            y[j] = fmaxf(a, 0.0f) + x[j];
        }
        #pragma unroll
        for (int j = 0; j < NN; j++) x[j] = y[j];
    }
    float tv[3];
    #pragma unroll
    for (int k = 0; k < 3; k++) {
        const float4* wr = reinterpret_cast<const float4*>(&s[S_A1 + k * 32]);
        float a = 0.0f;
        #pragma unroll
        for (int i = 0; i < 8; i++) {
            const float4 w = wr[i];
            a = fmaf(w.x, x[4 * i + 0], a);
            a = fmaf(w.y, x[4 * i + 1], a);
            a = fmaf(w.z, x[4 * i + 2], a);
            a = fmaf(w.w, x[4 * i + 3], a);
        }
        tv[k] = tanhf(a);
    }
    float resv[3];
    #pragma unroll
    for (int k = 0; k < 3; k++) {
        resv[k] = fmaf(s[S_B1 + k * 3 + 0], tv[0],
                  fmaf(s[S_B1 + k * 3 + 1], tv[1],
                       s[S_B1 + k * 3 + 2] * tv[2]));
    }
    const float pdx = px + resv[0];
    const float pdy = py + resv[1];
    const float pdz = pz + resv[2];

    // ---------------- outputs (non-image) ----------------
    if (write_extras) {
        out_posdef[idx * 3 + 0] = pdx;
        out_posdef[idx * 3 + 1] = pdy;
        out_posdef[idx * 3 + 2] = pdz;
        out_res[idx * 3 + 0] = resv[0];
        out_res[idx * 3 + 1] = resv[1];
        out_res[idx * 3 + 2] = resv[2];
        out_ampc[idx] = amp_corr;
    }

    // ---------------- project + splat ----------------
    const float* rb = &r[b * 9];
    const float proj0 = fmaf(rb[0], pdx, fmaf(rb[1], pdy, rb[2] * pdz));
    const float proj1 = fmaf(rb[3], pdx, fmaf(rb[4], pdy, rb[5] * pdz));

    const float amps = amp[0] * amp_corr;
    const float fx = (proj0 + 0.5f) * (float)(BOX - 1);
    const float fy = (proj1 + 0.5f) * (float)(BOX - 1);
    const int cx = __float2int_rn(fx);  // round-to-nearest-even, matches jnp.round
    const int cy = __float2int_rn(fy);

    float* img = out_img + (size_t)b * BOX * BOX;
    #pragma unroll
    for (int i = 0; i < KS; i++) {
        const int yy = cy + i - KS / 2;
        if ((unsigned)yy < (unsigned)BOX) {
            float* row = img + yy * BOX;
            #pragma unroll
            for (int j = 0; j < KS; j++) {
                const int xx = cx + j - KS / 2;
                if ((unsigned)xx < (unsigned)BOX) {
                    atomicAdd(row + xx, amps * s[S_K2 + i * KS + j]);
                }
            }
        }
    }
}

extern "C" void kernel_launch(void* const* d_in, const int* in_sizes, int n_in,
                              void* d_out, int out_size) {
    const float* z          = (const float*)d_in[0];
    const float* r          = (const float*)d_in[1];
    const float* pos        = (const float*)d_in[2];
    const float* amp        = (const float*)d_in[3];
    const float* linamp1_W  = (const float*)d_in[4];
    const float* ampblock_W = (const float*)d_in[5];
    const float* ampblock_b = (const float*)d_in[6];
    const float* linamp2_W  = (const float*)d_in[7];
    const float* linamp2_b  = (const float*)d_in[8];
    const float* lin0_W     = (const float*)d_in[9];
    const float* deform_W   = (const float*)d_in[10];
    const float* deform_b   = (const float*)d_in[11];
    const float* lin1a_W    = (const float*)d_in[12];
    const float* lin1b_W    = (const float*)d_in[13];
    const float* k2         = (const float*)d_in[14];
    // d_in[15] = d (always 1 for this problem)

    float* out = (float*)d_out;
    const long long IMG = (long long)NB * BOX * BOX;          // 1,048,576
    const long long PD  = (long long)NB * PNT * 3;            //   960,000
    const int write_extras = (out_size >= (int)(IMG + 2 * PD + (long long)NB * PNT)) ? 1 : 0;

    // Zero the image accumulation region (graph-capturable async memset)
    cudaMemsetAsync(out, 0, (size_t)IMG * sizeof(float));

    float* out_img    = out;
    float* out_posdef = out + IMG;
    float* out_res    = out + IMG + PD;
    float* out_ampc   = out + IMG + 2 * PD;

    const int total = NB * PNT;
    const int threads = 256;
    const int blocks = (total + threads - 1) / threads;
    decoder_kernel<<<blocks, threads>>>(
        z, r, pos, amp, linamp1_W, ampblock_W, ampblock_b, linamp2_W,
        linamp2_b, lin0_W, deform_W, deform_b, lin1a_W, lin1b_W, k2,
        out_img, out_posdef, out_res, out_ampc, write_extras);
}

// round 4
// speedup vs baseline: 1.5149x; 1.5149x over previous
#include <cuda_runtime.h>
#include <cuda_bf16.h>

#define BOX 256
#define KS 9
#define PNT 20000
#define NB 16
#define NN 32
#define NL 3
#define LAT 8

// Shared-memory layout offsets (floats)
#define S_W1   0        // linamp1_W   [32*4]   = 128
#define S_AW   128      // ampblock_W  [3*1024] = 3072
#define S_AB   3200     // ampblock_b  [96]
#define S_W2   3296     // linamp2_W   [32]
#define S_L0   3328     // lin0_W      [320]
#define S_DW   3648     // deform_W    [3072]
#define S_DB   6720     // deform_b    [96]
#define S_A1   6816     // lin1a_W     [96]
#define S_B1   6912     // lin1b_W     [9]
#define S_K2   6921     // k2          [81]
#define S_TOT  7008

__device__ __forceinline__ void red_add_v4(float* addr, float a, float b,
                                           float c, float d) {
    asm volatile("red.global.add.v4.f32 [%0], {%1, %2, %3, %4};"
                 :: "l"(addr), "f"(a), "f"(b), "f"(c), "f"(d) : "memory");
}

__global__ __launch_bounds__(256) void decoder_kernel(
    const float* __restrict__ z,          // [16,8]
    const float* __restrict__ r,          // [16,3,3]
    const float* __restrict__ pos,        // [20000,3]
    const float* __restrict__ amp,        // [1]
    const float* __restrict__ linamp1_W,  // [32,4]
    const float* __restrict__ ampblock_W, // [3,32,32]
    const float* __restrict__ ampblock_b, // [3,32]
    const float* __restrict__ linamp2_W,  // [1,32]
    const float* __restrict__ linamp2_b,  // [1]
    const float* __restrict__ lin0_W,     // [32,10]
    const float* __restrict__ deform_W,   // [3,32,32]
    const float* __restrict__ deform_b,   // [3,32]
    const float* __restrict__ lin1a_W,    // [3,32]
    const float* __restrict__ lin1b_W,    // [3,3]
    const float* __restrict__ k2,         // [9,9]
    float* __restrict__ out_img,          // [16,256,256]
    float* __restrict__ out_posdef,       // [16,20000,3]
    float* __restrict__ out_res,          // [16,20000,3]
    float* __restrict__ out_ampc,         // [16,20000]
    int write_extras)
{
    __shared__ float s[S_TOT];
    const int t = threadIdx.x;

    // Cooperative weight staging
    for (int i = t; i < 128;  i += 256) s[S_W1 + i] = linamp1_W[i];
    for (int i = t; i < 3072; i += 256) s[S_AW + i] = ampblock_W[i];
    for (int i = t; i < 96;   i += 256) s[S_AB + i] = ampblock_b[i];
    for (int i = t; i < 32;   i += 256) s[S_W2 + i] = linamp2_W[i];
    for (int i = t; i < 320;  i += 256) s[S_L0 + i] = lin0_W[i];
    for (int i = t; i < 3072; i += 256) s[S_DW + i] = deform_W[i];
    for (int i = t; i < 96;   i += 256) s[S_DB + i] = deform_b[i];
    for (int i = t; i < 96;   i += 256) s[S_A1 + i] = lin1a_W[i];
    for (int i = t; i < 9;    i += 256) s[S_B1 + i] = lin1b_W[i];
    for (int i = t; i < 81;   i += 256) s[S_K2 + i] = k2[i];
    __syncthreads();

    const int idx = blockIdx.x * 256 + t;
    if (idx >= NB * PNT) return;
    const int b = idx / PNT;
    const int p = idx - b * PNT;

    const float px = pos[p * 3 + 0];
    const float py = pos[p * 3 + 1];
    const float pz = pos[p * 3 + 2];

    float x[NN];
    float y[NN];

    // ---------------- amplitude head ----------------
    {
        const float cz = z[b * LAT + (LAT - 1)];
        #pragma unroll
        for (int j = 0; j < NN; j++) {
            const float4 w = *reinterpret_cast<const float4*>(&s[S_W1 + j * 4]);
            x[j] = fmaf(w.x, px, fmaf(w.y, py, fmaf(w.z, pz, w.w * cz)));
        }
        #pragma unroll
        for (int l = 0; l < NL; l++) {
            #pragma unroll
            for (int j = 0; j < NN; j++) {
                const float4* wr = reinterpret_cast<const float4*>(&s[S_AW + l * 1024 + j * 32]);
                float a = s[S_AB + l * 32 + j];
                #pragma unroll
                for (int i = 0; i < 8; i++) {
                    const float4 w = wr[i];
                    a = fmaf(w.x, x[4 * i + 0], a);
                    a = fmaf(w.y, x[4 * i + 1], a);
                    a = fmaf(w.z, x[4 * i + 2], a);
                    a = fmaf(w.w, x[4 * i + 3], a);
                }
                y[j] = fmaxf(a, 0.0f) + x[j];
            }
            #pragma unroll
            for (int j = 0; j < NN; j++) x[j] = y[j];
        }
    }
    float sacc = linamp2_b[0];
    #pragma unroll
    for (int j = 0; j < NN; j++) sacc = fmaf(s[S_W2 + j], x[j], sacc);
    const float amp_corr = 1.0f / (1.0f + expf(-sacc));

    // ---------------- deformation head ----------------
    float in10[10];
    in10[0] = px; in10[1] = py; in10[2] = pz;
    #pragma unroll
    for (int i = 0; i < LAT - 1; i++) in10[3 + i] = z[b * LAT + i];

    #pragma unroll
    for (int j = 0; j < NN; j++) {
        const float* wr = &s[S_L0 + j * 10];
        float a = 0.0f;
        #pragma unroll
        for (int i = 0; i < 10; i++) a = fmaf(wr[i], in10[i], a);
        x[j] = a;
    }
    #pragma unroll
    for (int l = 0; l < NL; l++) {
        #pragma unroll
        for (int j = 0; j < NN; j++) {
            const float4* wr = reinterpret_cast<const float4*>(&s[S_DW + l * 1024 + j * 32]);
            float a = s[S_DB + l * 32 + j];
            #pragma unroll
            for (int i = 0; i < 8; i++) {
                const float4 w = wr[i];
                a = fmaf(w.x, x[4 * i + 0], a);
                a = fmaf(w.y, x[4 * i + 1], a);
                a = fmaf(w.z, x[4 * i + 2], a);
                a = fmaf(w.w, x[4 * i + 3], a);
            }
            y[j] = fmaxf(a, 0.0f) + x[j];
        }
        #pragma unroll
        for (int j = 0; j < NN; j++) x[j] = y[j];
    }
    float tv[3];
    #pragma unroll
    for (int k = 0; k < 3; k++) {
        const float4* wr = reinterpret_cast<const float4*>(&s[S_A1 + k * 32]);
        float a = 0.0f;
        #pragma unroll
        for (int i = 0; i < 8; i++) {
            const float4 w = wr[i];
            a = fmaf(w.x, x[4 * i + 0], a);
            a = fmaf(w.y, x[4 * i + 1], a);
            a = fmaf(w.z, x[4 * i + 2], a);
            a = fmaf(w.w, x[4 * i + 3], a);
        }
        tv[k] = tanhf(a);
    }
    float resv[3];
    #pragma unroll
    for (int k = 0; k < 3; k++) {
        resv[k] = fmaf(s[S_B1 + k * 3 + 0], tv[0],
                  fmaf(s[S_B1 + k * 3 + 1], tv[1],
                       s[S_B1 + k * 3 + 2] * tv[2]));
    }
    const float pdx = px + resv[0];
    const float pdy = py + resv[1];
    const float pdz = pz + resv[2];

    // ---------------- outputs (non-image) ----------------
    if (write_extras) {
        out_posdef[idx * 3 + 0] = pdx;
        out_posdef[idx * 3 + 1] = pdy;
        out_posdef[idx * 3 + 2] = pdz;
        out_res[idx * 3 + 0] = resv[0];
        out_res[idx * 3 + 1] = resv[1];
        out_res[idx * 3 + 2] = resv[2];
        out_ampc[idx] = amp_corr;
    }

    // ---------------- project + splat (vectorized v4 reductions) ----------------
    const float* rb = &r[b * 9];
    const float proj0 = fmaf(rb[0], pdx, fmaf(rb[1], pdy, rb[2] * pdz));
    const float proj1 = fmaf(rb[3], pdx, fmaf(rb[4], pdy, rb[5] * pdz));

    const float amps = amp[0] * amp_corr;
    const float fx = (proj0 + 0.5f) * (float)(BOX - 1);
    const float fy = (proj1 + 0.5f) * (float)(BOX - 1);
    const int cx = __float2int_rn(fx);  // ties-to-even, matches jnp.round
    const int cy = __float2int_rn(fy);

    // x-window: kernel cols cover [cx-4, cx+4]. Align to 4: base bx, shift off in [0,3].
    // 12-wide zero-padded weight window -> 3 x red.v4 per row.
    const int bx  = (cx - 4) & ~3;
    const int off = (cx - 4) - bx;

    // chunk validity: chunks are 4-aligned; row bounds 0/256 are 4-aligned,
    // so each chunk is fully in or fully out.
    const bool v0 = (bx >= 0) && (bx < BOX);
    const bool v1 = (bx + 4 >= 0) && (bx + 4 < BOX);
    const bool v2 = (bx + 8 >= 0) && (bx + 8 < BOX);

    float w12[12];
    #pragma unroll
    for (int k = 0; k < 12; k++) w12[k] = 0.0f;

    float* img = out_img + (size_t)b * BOX * BOX;
    #pragma unroll
    for (int i = 0; i < KS; i++) {
        const int yy = cy + i - KS / 2;
        if ((unsigned)yy < (unsigned)BOX) {
            #pragma unroll
            for (int j = 0; j < KS; j++) {
                w12[off + j] = amps * s[S_K2 + i * KS + j];
            }
            float* row = img + yy * BOX;
            if (v0) red_add_v4(row + bx,     w12[0], w12[1], w12[2],  w12[3]);
            if (v1) red_add_v4(row + bx + 4, w12[4], w12[5], w12[6],  w12[7]);
            if (v2) red_add_v4(row + bx + 8, w12[8], w12[9], w12[10], w12[11]);
        }
    }
}

extern "C" void kernel_launch(void* const* d_in, const int* in_sizes, int n_in,
                              void* d_out, int out_size) {
    const float* z          = (const float*)d_in[0];
    const float* r          = (const float*)d_in[1];
    const float* pos        = (const float*)d_in[2];
    const float* amp        = (const float*)d_in[3];
    const float* linamp1_W  = (const float*)d_in[4];
    const float* ampblock_W = (const float*)d_in[5];
    const float* ampblock_b = (const float*)d_in[6];
    const float* linamp2_W  = (const float*)d_in[7];
    const float* linamp2_b  = (const float*)d_in[8];
    const float* lin0_W     = (const float*)d_in[9];
    const float* deform_W   = (const float*)d_in[10];
    const float* deform_b   = (const float*)d_in[11];
    const float* lin1a_W    = (const float*)d_in[12];
    const float* lin1b_W    = (const float*)d_in[13];
    const float* k2         = (const float*)d_in[14];
    // d_in[15] = d (always 1 for this problem)

    float* out = (float*)d_out;
    const long long IMG = (long long)NB * BOX * BOX;          // 1,048,576
    const long long PD  = (long long)NB * PNT * 3;            //   960,000
    const int write_extras = (out_size >= (int)(IMG + 2 * PD + (long long)NB * PNT)) ? 1 : 0;

    // Zero the image accumulation region (graph-capturable async memset)
    cudaMemsetAsync(out, 0, (size_t)IMG * sizeof(float));

    float* out_img    = out;
    float* out_posdef = out + IMG;
    float* out_res    = out + IMG + PD;
    float* out_ampc   = out + IMG + 2 * PD;

    const int total = NB * PNT;
    const int threads = 256;
    const int blocks = (total + threads - 1) / threads;
    decoder_kernel<<<blocks, threads>>>(
        z, r, pos, amp, linamp1_W, ampblock_W, ampblock_b, linamp2_W,
        linamp2_b, lin0_W, deform_W, deform_b, lin1a_W, lin1b_W, k2,
        out_img, out_posdef, out_res, out_ampc, write_extras);
}

// round 6
// speedup vs baseline: 1.5239x; 1.0059x over previous
#include <cuda_runtime.h>
#include <cuda_bf16.h>

#define BOX 256
#define KS 9
#define PNT 20000
#define NB 16
#define NN 32
#define NL 3
#define LAT 8

// Shared-memory layout offsets (floats)
#define S_W1   0        // linamp1_W   [32*4]   = 128
#define S_AW   128      // ampblock_W  [3*1024] = 3072
#define S_AB   3200     // ampblock_b  [96]
#define S_W2   3296     // linamp2_W   [32]
#define S_L0   3328     // lin0_W      [320]
#define S_DW   3648     // deform_W    [3072]
#define S_DB   6720     // deform_b    [96]
#define S_A1   6816     // lin1a_W     [96]
#define S_B1   6912     // lin1b_W     [9]
#define S_KP   6928     // k2pad       [4][9][12] = 432  (16B aligned: 6928*4=27712)
#define S_TOT  7360

__device__ __forceinline__ void red_add_v4(float* addr, float a, float b,
                                           float c, float d) {
    asm volatile("red.global.add.v4.f32 [%0], {%1, %2, %3, %4};"
                 :: "l"(addr), "f"(a), "f"(b), "f"(c), "f"(d) : "memory");
}

__global__ __launch_bounds__(256) void decoder_kernel(
    const float* __restrict__ z,          // [16,8]
    const float* __restrict__ r,          // [16,3,3]
    const float* __restrict__ pos,        // [20000,3]
    const float* __restrict__ amp,        // [1]
    const float* __restrict__ linamp1_W,  // [32,4]
    const float* __restrict__ ampblock_W, // [3,32,32]
    const float* __restrict__ ampblock_b, // [3,32]
    const float* __restrict__ linamp2_W,  // [1,32]
    const float* __restrict__ linamp2_b,  // [1]
    const float* __restrict__ lin0_W,     // [32,10]
    const float* __restrict__ deform_W,   // [3,32,32]
    const float* __restrict__ deform_b,   // [3,32]
    const float* __restrict__ lin1a_W,    // [3,32]
    const float* __restrict__ lin1b_W,    // [3,3]
    const float* __restrict__ k2,         // [9,9]
    float* __restrict__ out_img,          // [16,256,256]
    float* __restrict__ out_posdef,       // [16,20000,3]
    float* __restrict__ out_res,          // [16,20000,3]
    float* __restrict__ out_ampc,         // [16,20000]
    int write_extras)
{
    __shared__ float s[S_TOT];
    const int t = threadIdx.x;

    // Cooperative weight staging
    for (int i = t; i < 128;  i += 256) s[S_W1 + i] = linamp1_W[i];
    for (int i = t; i < 3072; i += 256) s[S_AW + i] = ampblock_W[i];
    for (int i = t; i < 96;   i += 256) s[S_AB + i] = ampblock_b[i];
    for (int i = t; i < 32;   i += 256) s[S_W2 + i] = linamp2_W[i];
    for (int i = t; i < 320;  i += 256) s[S_L0 + i] = lin0_W[i];
    for (int i = t; i < 3072; i += 256) s[S_DW + i] = deform_W[i];
    for (int i = t; i < 96;   i += 256) s[S_DB + i] = deform_b[i];
    for (int i = t; i < 96;   i += 256) s[S_A1 + i] = lin1a_W[i];
    for (int i = t; i < 9;    i += 256) s[S_B1 + i] = lin1b_W[i];
    // Shifted zero-padded kernel table: k2pad[off][row][12]
    //   k2pad[off][row][m] = (0 <= m-off < 9) ? k2[row*9 + (m-off)] : 0
    for (int i = t; i < 432; i += 256) {
        const int o   = i / 108;
        const int rem = i - o * 108;
        const int row = rem / 12;
        const int m   = rem - row * 12;
        const int j   = m - o;
        s[S_KP + i] = (j >= 0 && j < KS) ? k2[row * KS + j] : 0.0f;
    }
    __syncthreads();

    const int idx = blockIdx.x * 256 + t;
    if (idx >= NB * PNT) return;
    const int b = idx / PNT;
    const int p = idx - b * PNT;

    const float px = pos[p * 3 + 0];
    const float py = pos[p * 3 + 1];
    const float pz = pos[p * 3 + 2];

    float x[NN];
    float y[NN];

    // ---------------- amplitude head ----------------
    {
        const float cz = z[b * LAT + (LAT - 1)];
        #pragma unroll
        for (int j = 0; j < NN; j++) {
            const float4 w = *reinterpret_cast<const float4*>(&s[S_W1 + j * 4]);
            x[j] = fmaf(w.x, px, fmaf(w.y, py, fmaf(w.z, pz, w.w * cz)));
        }
        #pragma unroll
        for (int l = 0; l < NL; l++) {
            #pragma unroll
            for (int j = 0; j < NN; j++) {
                const float4* wr = reinterpret_cast<const float4*>(&s[S_AW + l * 1024 + j * 32]);
                float a = s[S_AB + l * 32 + j];
                #pragma unroll
                for (int i = 0; i < 8; i++) {
                    const float4 w = wr[i];
                    a = fmaf(w.x, x[4 * i + 0], a);
                    a = fmaf(w.y, x[4 * i + 1], a);
                    a = fmaf(w.z, x[4 * i + 2], a);
                    a = fmaf(w.w, x[4 * i + 3], a);
                }
                y[j] = fmaxf(a, 0.0f) + x[j];
            }
            #pragma unroll
            for (int j = 0; j < NN; j++) x[j] = y[j];
        }
    }
    float sacc = linamp2_b[0];
    #pragma unroll
    for (int j = 0; j < NN; j++) sacc = fmaf(s[S_W2 + j], x[j], sacc);
    const float amp_corr = 1.0f / (1.0f + expf(-sacc));

    // ---------------- deformation head ----------------
    float in10[10];
    in10[0] = px; in10[1] = py; in10[2] = pz;
    #pragma unroll
    for (int i = 0; i < LAT - 1; i++) in10[3 + i] = z[b * LAT + i];

    #pragma unroll
    for (int j = 0; j < NN; j++) {
        const float* wr = &s[S_L0 + j * 10];
        float a = 0.0f;
        #pragma unroll
        for (int i = 0; i < 10; i++) a = fmaf(wr[i], in10[i], a);
        x[j] = a;
    }
    #pragma unroll
    for (int l = 0; l < NL; l++) {
        #pragma unroll
        for (int j = 0; j < NN; j++) {
            const float4* wr = reinterpret_cast<const float4*>(&s[S_DW + l * 1024 + j * 32]);
            float a = s[S_DB + l * 32 + j];
            #pragma unroll
            for (int i = 0; i < 8; i++) {
                const float4 w = wr[i];
                a = fmaf(w.x, x[4 * i + 0], a);
                a = fmaf(w.y, x[4 * i + 1], a);
                a = fmaf(w.z, x[4 * i + 2], a);
                a = fmaf(w.w, x[4 * i + 3], a);
            }
            y[j] = fmaxf(a, 0.0f) + x[j];
        }
        #pragma unroll
        for (int j = 0; j < NN; j++) x[j] = y[j];
    }
    float tv[3];
    #pragma unroll
    for (int k = 0; k < 3; k++) {
        const float4* wr = reinterpret_cast<const float4*>(&s[S_A1 + k * 32]);
        float a = 0.0f;
        #pragma unroll
        for (int i = 0; i < 8; i++) {
            const float4 w = wr[i];
            a = fmaf(w.x, x[4 * i + 0], a);
            a = fmaf(w.y, x[4 * i + 1], a);
            a = fmaf(w.z, x[4 * i + 2], a);
            a = fmaf(w.w, x[4 * i + 3], a);
        }
        tv[k] = tanhf(a);
    }
    float resv[3];
    #pragma unroll
    for (int k = 0; k < 3; k++) {
        resv[k] = fmaf(s[S_B1 + k * 3 + 0], tv[0],
                  fmaf(s[S_B1 + k * 3 + 1], tv[1],
                       s[S_B1 + k * 3 + 2] * tv[2]));
    }
    const float pdx = px + resv[0];
    const float pdy = py + resv[1];
    const float pdz = pz + resv[2];

    // ---------------- outputs (non-image) ----------------
    if (write_extras) {
        out_posdef[idx * 3 + 0] = pdx;
        out_posdef[idx * 3 + 1] = pdy;
        out_posdef[idx * 3 + 2] = pdz;
        out_res[idx * 3 + 0] = resv[0];
        out_res[idx * 3 + 1] = resv[1];
        out_res[idx * 3 + 2] = resv[2];
        out_ampc[idx] = amp_corr;
    }

    // ---------------- project + splat (static-indexed, v4 reductions) -------
    const float* rb = &r[b * 9];
    const float proj0 = fmaf(rb[0], pdx, fmaf(rb[1], pdy, rb[2] * pdz));
    const float proj1 = fmaf(rb[3], pdx, fmaf(rb[4], pdy, rb[5] * pdz));

    const float amps = amp[0] * amp_corr;
    const float fx = (proj0 + 0.5f) * (float)(BOX - 1);
    const float fy = (proj1 + 0.5f) * (float)(BOX - 1);
    const int cx = __float2int_rn(fx);  // ties-to-even, matches jnp.round
    const int cy = __float2int_rn(fy);

    // x-window: kernel cols cover [cx-4, cx+4]. Align to 4: base bx, shift off.
    const int bx  = (cx - 4) & ~3;
    const int off = (cx - 4) - bx;

    // chunk validity: 4-aligned chunks vs 4-aligned row bounds -> all-or-nothing
    const bool v0 = (bx >= 0) && (bx < BOX);
    const bool v1 = (bx + 4 >= 0) && (bx + 4 < BOX);
    const bool v2 = (bx + 8 >= 0) && (bx + 8 < BOX);

    // off only selects a base pointer into the precomputed padded table:
    // no dynamic register indexing anywhere in the splat loop.
    const float* kp = &s[S_KP + off * 108];

    float* img = out_img + (size_t)b * BOX * BOX;
    #pragma unroll
    for (int i = 0; i < KS; i++) {
        const int yy = cy + i - KS / 2;
        if ((unsigned)yy < (unsigned)BOX) {
            const float4 w0 = *reinterpret_cast<const float4*>(kp + i * 12 + 0);
            const float4 w1 = *reinterpret_cast<const float4*>(kp + i * 12 + 4);
            const float4 w2 = *reinterpret_cast<const float4*>(kp + i * 12 + 8);
            float* row = img + yy * BOX;
            if (v0) red_add_v4(row + bx,
                               amps * w0.x, amps * w0.y, amps * w0.z, amps * w0.w);
            if (v1) red_add_v4(row + bx + 4,
                               amps * w1.x, amps * w1.y, amps * w1.z, amps * w1.w);
            if (v2) red_add_v4(row + bx + 8,
                               amps * w2.x, amps * w2.y, amps * w2.z, amps * w2.w);
        }
    }
}

extern "C" void kernel_launch(void* const* d_in, const int* in_sizes, int n_in,
                              void* d_out, int out_size) {
    const float* z          = (const float*)d_in[0];
    const float* r          = (const float*)d_in[1];
    const float* pos        = (const float*)d_in[2];
    const float* amp        = (const float*)d_in[3];
    const float* linamp1_W  = (const float*)d_in[4];
    const float* ampblock_W = (const float*)d_in[5];
    const float* ampblock_b = (const float*)d_in[6];
    const float* linamp2_W  = (const float*)d_in[7];
    const float* linamp2_b  = (const float*)d_in[8];
    const float* lin0_W     = (const float*)d_in[9];
    const float* deform_W   = (const float*)d_in[10];
    const float* deform_b   = (const float*)d_in[11];
    const float* lin1a_W    = (const float*)d_in[12];
    const float* lin1b_W    = (const float*)d_in[13];
    const float* k2         = (const float*)d_in[14];
    // d_in[15] = d (always 1 for this problem)

    float* out = (float*)d_out;
    const long long IMG = (long long)NB * BOX * BOX;          // 1,048,576
    const long long PD  = (long long)NB * PNT * 3;            //   960,000
    const int write_extras = (out_size >= (int)(IMG + 2 * PD + (long long)NB * PNT)) ? 1 : 0;

    // Zero the image accumulation region (graph-capturable async memset)
    cudaMemsetAsync(out, 0, (size_t)IMG * sizeof(float));

    float* out_img    = out;
    float* out_posdef = out + IMG;
    float* out_res    = out + IMG + PD;
    float* out_ampc   = out + IMG + 2 * PD;

    const int total = NB * PNT;
    const int threads = 256;
    const int blocks = (total + threads - 1) / threads;
    decoder_kernel<<<blocks, threads>>>(
        z, r, pos, amp, linamp1_W, ampblock_W, ampblock_b, linamp2_W,
        linamp2_b, lin0_W, deform_W, deform_b, lin1a_W, lin1b_W, k2,
        out_img, out_posdef, out_res, out_ampc, write_extras);
}